// round 15
// baseline (speedup 1.0000x reference)
#include <cuda_runtime.h>
#include <cuda_bf16.h>
#include <stdint.h>

#define B_DIM 32
#define S_DIM 2048
#define MD 128
#define LB 64
#define NW 2041          // S - RANK + 1
#define WTILE 64
#define CHUNKS 32        // chunks per batch
#define NTILES 1024      // 32 batches x 32 chunks
#define AT_STRIDE_U32 68 // 272B row -> conflict-free

#define RAW_ROWS 71
#define RAW_BYTES (RAW_ROWS * MD * 4)            // 36352
#define AT_BYTES  (WTILE * AT_STRIDE_U32 * 4)    // 17408
#define OFF_AT    RAW_BYTES
#define OFF_SRED  (RAW_BYTES + AT_BYTES)         // 53760
#define OFF_MBAR  (OFF_SRED + 64)                // 2 chunk barriers
#define OFF_TICK  (OFF_MBAR + 16)
#define SMEM_TOTAL (OFF_TICK + 16)               // ~53.9 KB -> 4 CTAs/SM

// Scratch (device globals: no allocations allowed)
__device__ float g_C64[LB * MD];     // C[w%64][m]
__device__ float g_G[MD * MD];       // G - I
__device__ float g_growdev[MD];      // per-row max |G - I|
__device__ float g_nksq[LB];
__device__ float g_part[NTILES];
__device__ unsigned int g_count;     // ticket; reset by last block

__device__ __forceinline__ void mbar_wait(uint32_t mbar) {
    uint32_t done;
    asm volatile(
        "{\n\t.reg .pred p;\n\t"
        "mbarrier.try_wait.parity.acquire.cta.shared::cta.b64 p, [%1], 0;\n\t"
        "selp.b32 %0, 1, 0, p;\n\t}"
        : "=r"(done) : "r"(mbar) : "memory");
    if (!done) {
        asm volatile(
            "{\n\t.reg .pred P1;\n\t"
            "WL_%=:\n\t"
            "mbarrier.try_wait.parity.acquire.cta.shared::cta.b64 P1, [%0], 0, 0x989680;\n\t"
            "@P1 bra.uni WD_%=;\n\t"
            "bra.uni WL_%=;\n\t"
            "WD_%=:\n\t}"
            :: "r"(mbar) : "memory");
    }
}

// ---------------- K1: setup (prep + gram merged) -------------------
__global__ void k_setup(const float* __restrict__ M,
                        const float* __restrict__ A,
                        const float* __restrict__ Bb) {
    int t = threadIdx.x;   // 0..127
    if (blockIdx.x < LB) {
        int l = blockIdx.x;
        __shared__ float nk[MD];
        __shared__ float red[MD];
        float v = A[t * LB + l] * Bb[l * MD + t];
        nk[t] = v;
        red[t] = v * v;
        __syncthreads();
        float c = 0.f;
#pragma unroll 8
        for (int n = 0; n < MD; n++) c += M[n * MD + t] * nk[n];
        g_C64[l * MD + t] = c;
        for (int s = 64; s > 0; s >>= 1) {
            if (t < s) red[t] += red[t + s];
            __syncthreads();
        }
        if (t == 0) g_nksq[l] = red[0];
    } else {
        int m = blockIdx.x - LB;
        float s = 0.f;
#pragma unroll 8
        for (int n = 0; n < MD; n++) s += M[n * MD + m] * M[n * MD + t];
        float gmi = s - ((t == m) ? 1.f : 0.f);    // G - I
        g_G[m * MD + t] = gmi;
        __shared__ float red[MD];
        red[t] = fabsf(gmi);
        __syncthreads();
        for (int st = 64; st > 0; st >>= 1) {
            if (t < st) red[t] = fmaxf(red[t], red[t + st]);
            __syncthreads();
        }
        if (t == 0) g_growdev[m] = red[0];
    }
}

// ---- phase 1 body: 8 windows per warp; returns cross (x) and selfq (y) ----
template <bool STORE>
__device__ __forceinline__ float2 phase1(const char* smem, uint32_t* At2,
                                         int wid, int lane, int wt) {
    const float4* raw4 = reinterpret_cast<const float4*>(smem);
    int ws = wid;                    // 8-window segment per warp
    const float4* rs = raw4 + (ws * 8) * 32 + lane;

    float4 run = make_float4(0.f, 0.f, 0.f, 0.f);
    float4 ring[8];
#pragma unroll
    for (int r = 0; r < 7; r++) {
        ring[r] = run;
        float4 v = rs[r * 32];
        run.x += v.x; run.y += v.y; run.z += v.z; run.w += v.w;
    }
    ring[7] = run;   // prefix through rows 0..6 (used by window j=7)

    float4 cr = make_float4(0.f, 0.f, 0.f, 0.f);
    float4 sq = make_float4(0.f, 0.f, 0.f, 0.f);
#pragma unroll
    for (int j = 0; j < 8; j++) {
        float4 v = rs[(j + 7) * 32];   // row <= ws*8+14 <= 70 (in SMEM)
        run.x += v.x; run.y += v.y; run.z += v.z; run.w += v.w;

        int wc = ws * 8 + j;           // window index within chunk (= w%64)
        float4 P0 = ring[j];           // ring never wraps for 8 windows
        float4 a;
        if (wc < wt) {
            a.x = (run.x - P0.x) * 0.125f;
            a.y = (run.y - P0.y) * 0.125f;
            a.z = (run.z - P0.z) * 0.125f;
            a.w = (run.w - P0.w) * 0.125f;
        } else {
            a = make_float4(0.f, 0.f, 0.f, 0.f);
        }

        float4 c = __ldg(reinterpret_cast<const float4*>(
            &g_C64[wc * MD + lane * 4]));
        cr.x += a.x * c.x; cr.y += a.y * c.y;
        cr.z += a.z * c.z; cr.w += a.w * c.w;
        sq.x += a.x * a.x; sq.y += a.y * a.y;
        sq.z += a.z * a.z; sq.w += a.w * a.w;

        if (STORE) {
            __nv_bfloat162 p0 = __floats2bfloat162_rn(a.x, a.y);
            __nv_bfloat162 p1 = __floats2bfloat162_rn(a.z, a.w);
            *reinterpret_cast<uint2*>(&At2[wc * AT_STRIDE_U32 + lane * 2]) =
                make_uint2(*reinterpret_cast<uint32_t*>(&p0),
                           *reinterpret_cast<uint32_t*>(&p1));
        }
    }
    return make_float2((cr.x + cr.y) + (cr.z + cr.w),
                       (sq.x + sq.y) + (sq.z + sq.w));
}

// ---------------- K2: main fused kernel --------------------
__global__ void __launch_bounds__(256, 4) k_main(const float* __restrict__ seq,
                                                 float* __restrict__ out) {
    extern __shared__ char smem[];
    uint32_t* At2  = reinterpret_cast<uint32_t*>(smem + OFF_AT);
    float*    sred = reinterpret_cast<float*>(smem + OFF_SRED);
    unsigned int* s_ticket = reinterpret_cast<unsigned int*>(smem + OFF_TICK);
    uint32_t smem_u32 = (uint32_t)__cvta_generic_to_shared(smem);
    uint32_t mbar0    = smem_u32 + OFF_MBAR;

    int tid  = threadIdx.x;
    int lane = tid & 31;
    int wid  = tid >> 5;

    int tile  = blockIdx.x;
    int b     = tile >> 5;           // 32 chunks per batch
    int chunk = tile & 31;
    int w0    = chunk * WTILE;
    int wt    = min(WTILE, NW - w0);
    int rows  = min(RAW_ROWS, S_DIM - w0);

    // ---- phase 0: chunked, pipelined TMA loads (rows [0,39) and [39,71)) ----
    if (tid == 0) {
#pragma unroll
        for (int k = 0; k < 2; k++)
            asm volatile("mbarrier.init.shared.b64 [%0], 1;"
                         :: "r"(mbar0 + k * 8) : "memory");
        asm volatile("fence.proxy.async.shared::cta;" ::: "memory");
    }
    __syncthreads();
    if (tid == 0) {
        const int cb[3] = {0, 39, 71};
        const float* src = seq + ((size_t)b * S_DIM + w0) * MD;
#pragma unroll
        for (int k = 0; k < 2; k++) {
            int r0 = cb[k];
            int r1 = min(cb[k + 1], rows);
            uint32_t nb = (r1 > r0) ? (uint32_t)(r1 - r0) * MD * 4 : 0u;
            asm volatile("mbarrier.arrive.expect_tx.shared.b64 _, [%0], %1;"
                         :: "r"(mbar0 + k * 8), "r"(nb) : "memory");
            if (nb)
                asm volatile(
                    "cp.async.bulk.shared::cta.global.mbarrier::complete_tx::bytes "
                    "[%0], [%1], %2, [%3];"
                    :: "r"(smem_u32 + (uint32_t)r0 * MD * 4),
                       "l"(src + (size_t)r0 * MD), "r"(nb),
                       "r"(mbar0 + k * 8) : "memory");
        }
    }

    int gflag = (tid < MD) ? (__ldg(&g_growdev[tid]) != 0.f ? 1 : 0) : 0;
    gflag = __syncthreads_or(gflag);   // uniform: 0 iff G == I

    // each warp waits only on the chunk barriers covering its rows
    {
        // warp ws reads rows [8ws, 8ws+14]
        mbar_wait(mbar0);                              // rows < 39 (warps 0-4 partly)
        if (wid * 8 + 14 >= 39) mbar_wait(mbar0 + 8);  // second chunk if needed
    }

    // ---- phase 1 (+ identity-part quadratic term) ----
    float cross, selfq, dot = 0.f;
    if (gflag) {
        float2 cs = phase1<true>(smem, At2, wid, lane, wt);
        cross = cs.x; selfq = cs.y;
    } else {
        float2 cs = phase1<false>(smem, At2, wid, lane, wt);
        cross = cs.x; selfq = cs.y;
    }

    // ---- fallback: Gram * (G - I) via ldmatrix + mma (skipped when G==I) ----
    if (gflag) {
        __syncthreads();
        int wm = (wid & 3) << 5;
        int wn = (wid >> 2) << 6;
        int g  = lane >> 2;
        int tc = lane & 3;

        float acc[2][8][4];
#pragma unroll
        for (int a = 0; a < 2; a++)
#pragma unroll
            for (int bb = 0; bb < 8; bb++)
#pragma unroll
                for (int c = 0; c < 4; c++) acc[a][bb][c] = 0.f;

        uint32_t at_base = smem_u32 + OFF_AT;
        const int ROWB = AT_STRIDE_U32 * 4;

        uint32_t a_addr[2];
        {
            int krow = ((lane >> 4) & 1) * 8 + (lane & 7);
            int moff = ((lane >> 3) & 1) * 8;
#pragma unroll
            for (int mt = 0; mt < 2; mt++)
                a_addr[mt] = at_base + krow * ROWB + (wm + mt * 16 + moff) * 2;
        }
        uint32_t b_addr[4];
        {
            int krow = ((lane >> 3) & 1) * 8 + (lane & 7);
            int noff = ((lane >> 4) & 1) * 8;
#pragma unroll
            for (int nb = 0; nb < 4; nb++)
                b_addr[nb] = at_base + krow * ROWB + (wn + nb * 16 + noff) * 2;
        }

#pragma unroll
        for (int ks = 0; ks < 4; ks++) {   // K = 64 windows
            uint32_t koff = ks * 16 * ROWB;
            uint32_t af[2][4], bq[4][4];
#pragma unroll
            for (int mt = 0; mt < 2; mt++)
                asm volatile(
                    "ldmatrix.sync.aligned.m8n8.x4.trans.shared.b16 {%0,%1,%2,%3}, [%4];"
                    : "=r"(af[mt][0]), "=r"(af[mt][1]),
                      "=r"(af[mt][2]), "=r"(af[mt][3])
                    : "r"(a_addr[mt] + koff));
#pragma unroll
            for (int nb = 0; nb < 4; nb++)
                asm volatile(
                    "ldmatrix.sync.aligned.m8n8.x4.trans.shared.b16 {%0,%1,%2,%3}, [%4];"
                    : "=r"(bq[nb][0]), "=r"(bq[nb][1]),
                      "=r"(bq[nb][2]), "=r"(bq[nb][3])
                    : "r"(b_addr[nb] + koff));
#pragma unroll
            for (int nt = 0; nt < 8; nt++) {
                uint32_t b0 = bq[nt >> 1][(nt & 1) * 2];
                uint32_t b1 = bq[nt >> 1][(nt & 1) * 2 + 1];
#pragma unroll
                for (int mt = 0; mt < 2; mt++)
                    asm volatile(
                        "mma.sync.aligned.m16n8k16.row.col.f32.bf16.bf16.f32 "
                        "{%0,%1,%2,%3}, {%4,%5,%6,%7}, {%8,%9}, {%0,%1,%2,%3};"
                        : "+f"(acc[mt][nt][0]), "+f"(acc[mt][nt][1]),
                          "+f"(acc[mt][nt][2]), "+f"(acc[mt][nt][3])
                        : "r"(af[mt][0]), "r"(af[mt][1]),
                          "r"(af[mt][2]), "r"(af[mt][3]),
                          "r"(b0), "r"(b1));
            }
        }

#pragma unroll
        for (int mt = 0; mt < 2; mt++)
#pragma unroll
            for (int nt = 0; nt < 8; nt++) {
                int r = wm + mt * 16 + g;
                int c = wn + nt * 8 + 2 * tc;
                float2 g0 = __ldg(reinterpret_cast<const float2*>(&g_G[r * MD + c]));
                float2 g1 = __ldg(reinterpret_cast<const float2*>(&g_G[(r + 8) * MD + c]));
                dot += acc[mt][nt][0] * g0.x + acc[mt][nt][1] * g0.y;
                dot += acc[mt][nt][2] * g1.x + acc[mt][nt][3] * g1.y;
            }
    }

    // ---- block reduce (selfq + dot - 2*cross) via shuffles ----
    float val = selfq + dot - 2.f * cross;
#pragma unroll
    for (int o = 16; o > 0; o >>= 1) val += __shfl_xor_sync(0xffffffffu, val, o);
    if (lane == 0) sred[wid] = val;
    __syncthreads();

    // ---- last-block final reduction (replay-safe ticket) ----
    if (tid == 0) {
        float t = 0.f;
#pragma unroll
        for (int i = 0; i < 8; i++) t += sred[i];
        g_part[blockIdx.x] = t;
        __threadfence();
        *s_ticket = atomicAdd(&g_count, 1u);
    }
    __syncthreads();
    if (*s_ticket == NTILES - 1) {
        float v = (g_part[tid] + g_part[tid + 256]) +
                  (g_part[tid + 512] + g_part[tid + 768]);
        if (tid < LB) {
            int cnt = (NW - 1 - tid) / 64 + 1;
            v += (float)B_DIM * (float)cnt * g_nksq[tid];
        }
#pragma unroll
        for (int o = 16; o > 0; o >>= 1) v += __shfl_xor_sync(0xffffffffu, v, o);
        if (lane == 0) sred[wid] = v;
        __syncthreads();
        if (tid == 0) {
            float t = 0.f;
#pragma unroll
            for (int i = 0; i < 8; i++) t += sred[i];
            out[0] = t * (float)(1.0 / (32.0 * 2041.0 * 128.0));
            g_count = 0u;
        }
    }
}

extern "C" void kernel_launch(void* const* d_in, const int* in_sizes, int n_in,
                              void* d_out, int out_size) {
    (void)in_sizes; (void)n_in; (void)out_size;
    const float* seq = (const float*)d_in[0];
    const float* M   = (const float*)d_in[1];
    const float* A   = (const float*)d_in[2];
    const float* Bb  = (const float*)d_in[3];
    float* out = (float*)d_out;

    static bool attr_done = false;
    if (!attr_done) {
        cudaFuncSetAttribute(k_main, cudaFuncAttributeMaxDynamicSharedMemorySize,
                             SMEM_TOTAL);
        attr_done = true;
    }

    k_setup<<<LB + MD, MD>>>(M, A, Bb);
    k_main<<<NTILES, 256, SMEM_TOTAL>>>(seq, out);
}

// round 16
// speedup vs baseline: 1.1364x; 1.1364x over previous
#include <cuda_runtime.h>
#include <cuda_bf16.h>
#include <stdint.h>

#define B_DIM 32
#define S_DIM 2048
#define MD 128
#define LB 64
#define NW 2041          // S - RANK + 1
#define WTILE 128
#define NTILES 512       // 32 batches x 16 chunks
#define AT_STRIDE_U32 68 // 272B row -> conflict-free

// Scratch (device globals: no allocations allowed)
__device__ float g_C64[LB * MD];     // C[w%64][m]
__device__ float g_G[MD * MD];       // G - I
__device__ float g_growdev[MD];      // per-row max |G - I|
__device__ float g_nksq[LB];
__device__ float g_part[NTILES];
__device__ unsigned int g_count;     // ticket; reset by last block

// ---------------- K1: setup (prep + gram merged) -------------------
__global__ void k_setup(const float* __restrict__ M,
                        const float* __restrict__ A,
                        const float* __restrict__ Bb) {
    int t = threadIdx.x;   // 0..127
    if (blockIdx.x < LB) {
        int l = blockIdx.x;
        __shared__ float nk[MD];
        __shared__ float red[MD];
        float v = A[t * LB + l] * Bb[l * MD + t];
        nk[t] = v;
        red[t] = v * v;
        __syncthreads();
        float c = 0.f;
#pragma unroll 8
        for (int n = 0; n < MD; n++) c += M[n * MD + t] * nk[n];
        g_C64[l * MD + t] = c;
        for (int s = 64; s > 0; s >>= 1) {
            if (t < s) red[t] += red[t + s];
            __syncthreads();
        }
        if (t == 0) g_nksq[l] = red[0];
    } else {
        int m = blockIdx.x - LB;
        float s = 0.f;
#pragma unroll 8
        for (int n = 0; n < MD; n++) s += M[n * MD + m] * M[n * MD + t];
        float gmi = s - ((t == m) ? 1.f : 0.f);    // G - I
        g_G[m * MD + t] = gmi;
        __shared__ float red[MD];
        red[t] = fabsf(gmi);
        __syncthreads();
        for (int st = 64; st > 0; st >>= 1) {
            if (t < st) red[t] = fmaxf(red[t], red[t + st]);
            __syncthreads();
        }
        if (t == 0) g_growdev[m] = red[0];
    }
}

// ---- phase 1 body: 16 windows/warp direct from GMEM; cross + selfq ----
template <bool STORE>
__device__ __forceinline__ float2 phase1(const float* __restrict__ seq,
                                         uint32_t* At2, int b, int w0,
                                         int wid, int lane, int wt) {
    int ws    = wid;                 // 16-window segment per warp
    int srow0 = w0 + ws * 16;
    const float4* g4 = reinterpret_cast<const float4*>(seq);
    size_t base = ((size_t)b * S_DIM + srow0) * 32 + lane;

    float4 run = make_float4(0.f, 0.f, 0.f, 0.f);
    float4 ring[8];
#pragma unroll
    for (int r = 0; r < 7; r++) {    // rows srow0..srow0+6 always < 2048
        ring[r] = run;
        float4 v = __ldg(&g4[base + (size_t)r * 32]);
        run.x += v.x; run.y += v.y; run.z += v.z; run.w += v.w;
    }
    ring[7] = run;   // prefix through rows 0..6 (used by window j=7)

    float4 cr = make_float4(0.f, 0.f, 0.f, 0.f);
    float4 sq = make_float4(0.f, 0.f, 0.f, 0.f);
#pragma unroll
    for (int j = 0; j < 16; j++) {
        float4 v = make_float4(0.f, 0.f, 0.f, 0.f);
        if (srow0 + j + 7 < S_DIM) v = __ldg(&g4[base + (size_t)(j + 7) * 32]);
        run.x += v.x; run.y += v.y; run.z += v.z; run.w += v.w;

        int wc = ws * 16 + j;
        float4 P0 = ring[j & 7];
        float4 a;
        if (wc < wt) {
            a.x = (run.x - P0.x) * 0.125f;
            a.y = (run.y - P0.y) * 0.125f;
            a.z = (run.z - P0.z) * 0.125f;
            a.w = (run.w - P0.w) * 0.125f;
        } else {
            a = make_float4(0.f, 0.f, 0.f, 0.f);
        }
        ring[j & 7] = run;

        float4 c = __ldg(reinterpret_cast<const float4*>(
            &g_C64[(wc & 63) * MD + lane * 4]));
        cr.x += a.x * c.x; cr.y += a.y * c.y;
        cr.z += a.z * c.z; cr.w += a.w * c.w;
        sq.x += a.x * a.x; sq.y += a.y * a.y;
        sq.z += a.z * a.z; sq.w += a.w * a.w;

        if (STORE) {
            __nv_bfloat162 p0 = __floats2bfloat162_rn(a.x, a.y);
            __nv_bfloat162 p1 = __floats2bfloat162_rn(a.z, a.w);
            *reinterpret_cast<uint2*>(&At2[wc * AT_STRIDE_U32 + lane * 2]) =
                make_uint2(*reinterpret_cast<uint32_t*>(&p0),
                           *reinterpret_cast<uint32_t*>(&p1));
        }
    }
    return make_float2((cr.x + cr.y) + (cr.z + cr.w),
                       (sq.x + sq.y) + (sq.z + sq.w));
}

// ---------------- K2: main fused kernel --------------------
__global__ void __launch_bounds__(256, 4) k_main(const float* __restrict__ seq,
                                                 float* __restrict__ out) {
    __shared__ uint32_t At2[WTILE * AT_STRIDE_U32];   // fallback only
    __shared__ float sred[8];
    __shared__ unsigned int s_ticket;

    int tid  = threadIdx.x;
    int lane = tid & 31;
    int wid  = tid >> 5;

    int tile  = blockIdx.x;
    int b     = tile >> 4;
    int chunk = tile & 15;
    int w0    = chunk * WTILE;
    int wt    = min(WTILE, NW - w0);

    int gflag = (tid < MD) ? (__ldg(&g_growdev[tid]) != 0.f ? 1 : 0) : 0;
    gflag = __syncthreads_or(gflag);   // uniform: 0 iff G == I

    // ---- phase 1: pure register streaming (no SMEM/sync on fast path) ----
    float cross, selfq, dot = 0.f;
    if (gflag) {
        float2 cs = phase1<true>(seq, At2, b, w0, wid, lane, wt);
        cross = cs.x; selfq = cs.y;
    } else {
        float2 cs = phase1<false>(seq, At2, b, w0, wid, lane, wt);
        cross = cs.x; selfq = cs.y;
    }

    // ---- fallback: Gram * (G - I) via ldmatrix + mma (skipped when G==I) ----
    if (gflag) {
        __syncthreads();
        int wm = (wid & 3) << 5;
        int wn = (wid >> 2) << 6;
        int g  = lane >> 2;
        int tc = lane & 3;

        float acc[2][8][4];
#pragma unroll
        for (int a = 0; a < 2; a++)
#pragma unroll
            for (int bb = 0; bb < 8; bb++)
#pragma unroll
                for (int c = 0; c < 4; c++) acc[a][bb][c] = 0.f;

        uint32_t at_base = (uint32_t)__cvta_generic_to_shared(At2);
        const int ROWB = AT_STRIDE_U32 * 4;

        uint32_t a_addr[2];
        {
            int krow = ((lane >> 4) & 1) * 8 + (lane & 7);
            int moff = ((lane >> 3) & 1) * 8;
#pragma unroll
            for (int mt = 0; mt < 2; mt++)
                a_addr[mt] = at_base + krow * ROWB + (wm + mt * 16 + moff) * 2;
        }
        uint32_t b_addr[4];
        {
            int krow = ((lane >> 3) & 1) * 8 + (lane & 7);
            int noff = ((lane >> 4) & 1) * 8;
#pragma unroll
            for (int nb = 0; nb < 4; nb++)
                b_addr[nb] = at_base + krow * ROWB + (wn + nb * 16 + noff) * 2;
        }

#pragma unroll
        for (int ks = 0; ks < 8; ks++) {
            uint32_t koff = ks * 16 * ROWB;
            uint32_t af[2][4], bq[4][4];
#pragma unroll
            for (int mt = 0; mt < 2; mt++)
                asm volatile(
                    "ldmatrix.sync.aligned.m8n8.x4.trans.shared.b16 {%0,%1,%2,%3}, [%4];"
                    : "=r"(af[mt][0]), "=r"(af[mt][1]),
                      "=r"(af[mt][2]), "=r"(af[mt][3])
                    : "r"(a_addr[mt] + koff));
#pragma unroll
            for (int nb = 0; nb < 4; nb++)
                asm volatile(
                    "ldmatrix.sync.aligned.m8n8.x4.trans.shared.b16 {%0,%1,%2,%3}, [%4];"
                    : "=r"(bq[nb][0]), "=r"(bq[nb][1]),
                      "=r"(bq[nb][2]), "=r"(bq[nb][3])
                    : "r"(b_addr[nb] + koff));
#pragma unroll
            for (int nt = 0; nt < 8; nt++) {
                uint32_t b0 = bq[nt >> 1][(nt & 1) * 2];
                uint32_t b1 = bq[nt >> 1][(nt & 1) * 2 + 1];
#pragma unroll
                for (int mt = 0; mt < 2; mt++)
                    asm volatile(
                        "mma.sync.aligned.m16n8k16.row.col.f32.bf16.bf16.f32 "
                        "{%0,%1,%2,%3}, {%4,%5,%6,%7}, {%8,%9}, {%0,%1,%2,%3};"
                        : "+f"(acc[mt][nt][0]), "+f"(acc[mt][nt][1]),
                          "+f"(acc[mt][nt][2]), "+f"(acc[mt][nt][3])
                        : "r"(af[mt][0]), "r"(af[mt][1]),
                          "r"(af[mt][2]), "r"(af[mt][3]),
                          "r"(b0), "r"(b1));
            }
        }

#pragma unroll
        for (int mt = 0; mt < 2; mt++)
#pragma unroll
            for (int nt = 0; nt < 8; nt++) {
                int r = wm + mt * 16 + g;
                int c = wn + nt * 8 + 2 * tc;
                float2 g0 = __ldg(reinterpret_cast<const float2*>(&g_G[r * MD + c]));
                float2 g1 = __ldg(reinterpret_cast<const float2*>(&g_G[(r + 8) * MD + c]));
                dot += acc[mt][nt][0] * g0.x + acc[mt][nt][1] * g0.y;
                dot += acc[mt][nt][2] * g1.x + acc[mt][nt][3] * g1.y;
            }
    }

    // ---- block reduce (selfq + dot - 2*cross) via shuffles ----
    float val = selfq + dot - 2.f * cross;
#pragma unroll
    for (int o = 16; o > 0; o >>= 1) val += __shfl_xor_sync(0xffffffffu, val, o);
    if (lane == 0) sred[wid] = val;
    __syncthreads();

    // ---- last-block final reduction (replay-safe ticket) ----
    if (tid == 0) {
        float t = 0.f;
#pragma unroll
        for (int i = 0; i < 8; i++) t += sred[i];
        g_part[blockIdx.x] = t;
        __threadfence();
        s_ticket = atomicAdd(&g_count, 1u);
    }
    __syncthreads();
    if (s_ticket == NTILES - 1) {
        float v = g_part[tid] + g_part[tid + 256];
        if (tid < LB) {
            int cnt = (NW - 1 - tid) / 64 + 1;
            v += (float)B_DIM * (float)cnt * g_nksq[tid];
        }
#pragma unroll
        for (int o = 16; o > 0; o >>= 1) v += __shfl_xor_sync(0xffffffffu, v, o);
        if (lane == 0) sred[wid] = v;
        __syncthreads();
        if (tid == 0) {
            float t = 0.f;
#pragma unroll
            for (int i = 0; i < 8; i++) t += sred[i];
            out[0] = t * (float)(1.0 / (32.0 * 2041.0 * 128.0));
            g_count = 0u;
        }
    }
}

extern "C" void kernel_launch(void* const* d_in, const int* in_sizes, int n_in,
                              void* d_out, int out_size) {
    (void)in_sizes; (void)n_in; (void)out_size;
    const float* seq = (const float*)d_in[0];
    const float* M   = (const float*)d_in[1];
    const float* A   = (const float*)d_in[2];
    const float* Bb  = (const float*)d_in[3];
    float* out = (float*)d_out;

    k_setup<<<LB + MD, MD>>>(M, A, Bb);
    k_main<<<NTILES, 256>>>(seq, out);
}